// round 2
// baseline (speedup 1.0000x reference)
#include <cuda_runtime.h>
#include <cstdint>

#define SCALE_F 0.17677669529663687f

// ---------------- scratch ----------------
__device__ float g_q[2097152];        // [B,H,N,D]
__device__ float g_k[2097152];
__device__ float g_v[2097152];
__device__ float g_attn[33554432];    // [B,H,N,N]
__device__ float g_max[65536];        // [B*H*N]
__device__ float g_invden[65536];
__device__ float g_node1[2097152];    // [B,N,C]
__device__ float g_wred[262144];      // [B,N,E]

// ---------------- generic 128x128 SGEMM: out = A @ W^T (+bias) ----------------
// EPI 0: QKV scatter to g_q/g_k/g_v.  EPI 1: g_node1 += g_wred@W^T + bias.
// EPI 2: Cout = g_node1@W^T + bias.
template<int EPI>
__global__ __launch_bounds__(256)
void sgemm_kernel(const float* __restrict__ A, const float* __restrict__ W,
                  const float* __restrict__ bias, float* __restrict__ Cout, int K)
{
    __shared__ float As[8][128];
    __shared__ float Ws[8][128];
    const int tid = threadIdx.x;
    const int bm = blockIdx.y << 7;
    const int bn = blockIdx.x << 7;
    const int lr = tid >> 1;
    const int lc = (tid & 1) << 2;
    const int tm = (tid >> 4) << 3;
    const int tn = (tid & 15) << 3;

    const float* Ab = (EPI == 1) ? (const float*)g_wred
                    : (EPI == 2) ? (const float*)g_node1 : A;

    float acc[8][8];
#pragma unroll
    for (int i = 0; i < 8; i++)
#pragma unroll
        for (int j = 0; j < 8; j++) acc[i][j] = 0.f;

    const float* Ap = Ab + (size_t)(bm + lr) * K + lc;
    const float* Wp = W  + (size_t)(bn + lr) * K + lc;

    for (int k0 = 0; k0 < K; k0 += 8) {
        float4 av = *(const float4*)(Ap + k0);
        float4 wv = *(const float4*)(Wp + k0);
        As[lc + 0][lr] = av.x; As[lc + 1][lr] = av.y;
        As[lc + 2][lr] = av.z; As[lc + 3][lr] = av.w;
        Ws[lc + 0][lr] = wv.x; Ws[lc + 1][lr] = wv.y;
        Ws[lc + 2][lr] = wv.z; Ws[lc + 3][lr] = wv.w;
        __syncthreads();
#pragma unroll
        for (int kk = 0; kk < 8; kk++) {
            float a[8], b[8];
            float4 t0 = *(const float4*)&As[kk][tm];
            float4 t1 = *(const float4*)&As[kk][tm + 4];
            float4 t2 = *(const float4*)&Ws[kk][tn];
            float4 t3 = *(const float4*)&Ws[kk][tn + 4];
            a[0]=t0.x; a[1]=t0.y; a[2]=t0.z; a[3]=t0.w;
            a[4]=t1.x; a[5]=t1.y; a[6]=t1.z; a[7]=t1.w;
            b[0]=t2.x; b[1]=t2.y; b[2]=t2.z; b[3]=t2.w;
            b[4]=t3.x; b[5]=t3.y; b[6]=t3.z; b[7]=t3.w;
#pragma unroll
            for (int i = 0; i < 8; i++)
#pragma unroll
                for (int j = 0; j < 8; j++)
                    acc[i][j] = fmaf(a[i], b[j], acc[i][j]);
        }
        __syncthreads();
    }

    const int col0 = bn + tn;
    float4 bv0 = *(const float4*)&bias[col0];
    float4 bv1 = *(const float4*)&bias[col0 + 4];

    if (EPI == 0) {
        int s  = col0 >> 9;
        int hd = col0 & 511;
        float* base = (s == 0 ? g_q : (s == 1 ? g_k : g_v));
#pragma unroll
        for (int i = 0; i < 8; i++) {
            int row = bm + tm + i;
            int b_  = row >> 9, n = row & 511;
            float* dst = base + ((size_t)((b_ << 4) + (hd >> 5)) << 14) + (n << 5) + (hd & 31);
            float4 o0, o1;
            o0.x = acc[i][0] + bv0.x; o0.y = acc[i][1] + bv0.y;
            o0.z = acc[i][2] + bv0.z; o0.w = acc[i][3] + bv0.w;
            o1.x = acc[i][4] + bv1.x; o1.y = acc[i][5] + bv1.y;
            o1.z = acc[i][6] + bv1.z; o1.w = acc[i][7] + bv1.w;
            *(float4*)dst = o0; *(float4*)(dst + 4) = o1;
        }
    } else {
        float* Cb = (EPI == 1) ? (float*)g_node1 : Cout;
#pragma unroll
        for (int i = 0; i < 8; i++) {
            int row = bm + tm + i;
            float* dst = Cb + ((size_t)row << 9) + col0;
            float4 o0, o1;
            o0.x = acc[i][0] + bv0.x; o0.y = acc[i][1] + bv0.y;
            o0.z = acc[i][2] + bv0.z; o0.w = acc[i][3] + bv0.w;
            o1.x = acc[i][4] + bv1.x; o1.y = acc[i][5] + bv1.y;
            o1.z = acc[i][6] + bv1.z; o1.w = acc[i][7] + bv1.w;
            if (EPI == 1) {
                float4 c0 = *(const float4*)dst;
                float4 c1 = *(const float4*)(dst + 4);
                o0.x += c0.x; o0.y += c0.y; o0.z += c0.z; o0.w += c0.w;
                o1.x += c1.x; o1.y += c1.y; o1.z += c1.z; o1.w += c1.w;
            }
            *(float4*)dst = o0; *(float4*)(dst + 4) = o1;
        }
    }
}

// ---------------- attn = sum_e edge[b,e,n,m]*rw[h,e] + rb[h] ----------------
__global__ __launch_bounds__(128)
void bias_kernel(const float* __restrict__ edge, const float* __restrict__ rw,
                 const float* __restrict__ rb)
{
    __shared__ float s_rw[1024];
    __shared__ float s_rb[16];
    const int tid = threadIdx.x;
    const int n = blockIdx.x, b = blockIdx.y;
    for (int i = tid; i < 1024; i += 128) s_rw[i] = rw[i];
    if (tid < 16) s_rb[tid] = rb[tid];
    __syncthreads();

    const int m0 = tid << 2;
    float acc[16][4];
#pragma unroll
    for (int h = 0; h < 16; h++)
#pragma unroll
        for (int j = 0; j < 4; j++) acc[h][j] = 0.f;

    const float* ep = edge + (size_t)b * 16777216 + (size_t)n * 512 + m0;
#pragma unroll 4
    for (int e = 0; e < 64; e++) {
        float4 v = *(const float4*)(ep + (size_t)e * 262144);
#pragma unroll
        for (int h = 0; h < 16; h++) {
            float w = s_rw[(h << 6) + e];
            acc[h][0] = fmaf(w, v.x, acc[h][0]);
            acc[h][1] = fmaf(w, v.y, acc[h][1]);
            acc[h][2] = fmaf(w, v.z, acc[h][2]);
            acc[h][3] = fmaf(w, v.w, acc[h][3]);
        }
    }
    float* op = g_attn + (size_t)b * 4194304 + (size_t)n * 512 + m0;
#pragma unroll
    for (int h = 0; h < 16; h++) {
        float rv = s_rb[h];
        float4 o = {acc[h][0] + rv, acc[h][1] + rv, acc[h][2] + rv, acc[h][3] + rv};
        *(float4*)(op + (size_t)h * 262144) = o;
    }
}

// ---------------- attn += SCALE * q@k^T, per (b,h), 64x64 tiles ----------------
__global__ __launch_bounds__(256)
void scores_kernel()
{
    __shared__ float Qs[64][33];
    __shared__ float Ks[64][33];
    const int tid = threadIdx.x;
    const int bh = blockIdx.z;
    const int n0 = blockIdx.y << 6;
    const int m0 = blockIdx.x << 6;
    const float* qp = g_q + (size_t)bh * 16384;
    const float* kp = g_k + (size_t)bh * 16384;

    const int r = tid >> 2;
    const int c = (tid & 3) << 3;
    {
        float4 q1 = *(const float4*)(qp + (size_t)(n0 + r) * 32 + c);
        float4 q2 = *(const float4*)(qp + (size_t)(n0 + r) * 32 + c + 4);
        Qs[r][c+0]=q1.x; Qs[r][c+1]=q1.y; Qs[r][c+2]=q1.z; Qs[r][c+3]=q1.w;
        Qs[r][c+4]=q2.x; Qs[r][c+5]=q2.y; Qs[r][c+6]=q2.z; Qs[r][c+7]=q2.w;
        float4 k1 = *(const float4*)(kp + (size_t)(m0 + r) * 32 + c);
        float4 k2 = *(const float4*)(kp + (size_t)(m0 + r) * 32 + c + 4);
        Ks[r][c+0]=k1.x; Ks[r][c+1]=k1.y; Ks[r][c+2]=k1.z; Ks[r][c+3]=k1.w;
        Ks[r][c+4]=k2.x; Ks[r][c+5]=k2.y; Ks[r][c+6]=k2.z; Ks[r][c+7]=k2.w;
    }
    __syncthreads();

    const int tn = (tid >> 4) << 2;
    const int tm = (tid & 15) << 2;
    float acc[4][4];
#pragma unroll
    for (int i = 0; i < 4; i++)
#pragma unroll
        for (int j = 0; j < 4; j++) acc[i][j] = 0.f;

#pragma unroll
    for (int d = 0; d < 32; d++) {
        float a[4], bv[4];
#pragma unroll
        for (int i = 0; i < 4; i++) { a[i] = Qs[tn + i][d]; bv[i] = Ks[tm + i][d]; }
#pragma unroll
        for (int i = 0; i < 4; i++)
#pragma unroll
            for (int j = 0; j < 4; j++)
                acc[i][j] = fmaf(a[i], bv[j], acc[i][j]);
    }

    float* op = g_attn + ((size_t)bh * 512 + n0 + tn) * 512 + m0 + tm;
#pragma unroll
    for (int i = 0; i < 4; i++) {
        float4 cur = *(float4*)(op + (size_t)i * 512);
        cur.x += SCALE_F * acc[i][0];
        cur.y += SCALE_F * acc[i][1];
        cur.z += SCALE_F * acc[i][2];
        cur.w += SCALE_F * acc[i][3];
        *(float4*)(op + (size_t)i * 512) = cur;
    }
}

// ---------------- softmax row stats over m (masked) ----------------
__global__ __launch_bounds__(128)
void stats_kernel(const unsigned char* __restrict__ mask)
{
    __shared__ float sred[128];
    const int row = blockIdx.x;            // (b*16+h)*512+n
    const int b = row >> 13;
    const int tid = threadIdx.x;
    const float* ap = g_attn + (size_t)row * 512;
    const unsigned char* mp = mask + (b << 9) + (tid << 2);
    float4 v = *(const float4*)(ap + (tid << 2));
    unsigned char k0 = mp[0], k1 = mp[1], k2 = mp[2], k3 = mp[3];
    float x0 = k0 ? -3.0e38f : v.x;
    float x1 = k1 ? -3.0e38f : v.y;
    float x2 = k2 ? -3.0e38f : v.z;
    float x3 = k3 ? -3.0e38f : v.w;
    float lm = fmaxf(fmaxf(x0, x1), fmaxf(x2, x3));
    sred[tid] = lm; __syncthreads();
    for (int s = 64; s > 0; s >>= 1) {
        if (tid < s) sred[tid] = fmaxf(sred[tid], sred[tid + s]);
        __syncthreads();
    }
    float M = sred[0];
    __syncthreads();
    float ls = 0.f;
    if (!k0) ls += __expf(v.x - M);
    if (!k1) ls += __expf(v.y - M);
    if (!k2) ls += __expf(v.z - M);
    if (!k3) ls += __expf(v.w - M);
    sred[tid] = ls; __syncthreads();
    for (int s = 64; s > 0; s >>= 1) {
        if (tid < s) sred[tid] += sred[tid + s];
        __syncthreads();
    }
    if (tid == 0) { g_max[row] = M; g_invden[row] = 1.0f / sred[0]; }
}

// ---------------- edge path: t = a+attn; edge_out = expand(t)+eb; online edge softmax -> g_wred
__global__ __launch_bounds__(256)
void edge_kernel(const unsigned char* __restrict__ mask,
                 const float* __restrict__ ew, const float* __restrict__ eb,
                 float* __restrict__ out_edge)
{
    __shared__ float t_s[16][516];
    __shared__ float ewS[64][17];
    __shared__ float eb_s[64];
    __shared__ float M_s[16], L_s[16];
    __shared__ unsigned char mk[512];
    const int tid = threadIdx.x;
    const int n = blockIdx.x, b = blockIdx.y;

    for (int i = tid; i < 1024; i += 256) { ewS[i >> 4][i & 15] = ew[i]; }
    if (tid < 64) eb_s[tid] = eb[tid];
    if (tid < 16) {
        int row = (b * 16 + tid) * 512 + n;
        M_s[tid] = g_max[row];
        L_s[tid] = g_invden[row];
    }
    mk[tid] = mask[(b << 9) + tid];
    mk[tid + 256] = mask[(b << 9) + tid + 256];
    __syncthreads();

    // phase 1: t[h][m] = a + attn
    for (int mm = tid; mm < 512; mm += 256) {
        bool k = mk[mm] != 0;
        const float* ap = g_attn + (size_t)b * 4194304 + (size_t)n * 512 + mm;
#pragma unroll
        for (int h = 0; h < 16; h++) {
            float x = ap[(size_t)h * 262144];
            float a = k ? 0.f : __expf(x - M_s[h]) * L_s[h];
            t_s[h][mm] = a + x;
        }
    }
    __syncthreads();

    // phase 2: each thread: one e, 128 m (interleaved float4 chunks)
    const int e = tid >> 2, mg = tid & 3;
    float w[16];
#pragma unroll
    for (int h = 0; h < 16; h++) w[h] = ewS[e][h];
    const float be = eb_s[e];
    float* op = out_edge + ((size_t)b * 64 + e) * 262144 + (size_t)n * 512;

    float M = -1e30f, S1 = 0.f, S2 = 0.f;
#pragma unroll 4
    for (int j = 0; j < 32; j++) {
        const int m0 = (mg << 2) + (j << 4);
        float4 o = {be, be, be, be};
#pragma unroll
        for (int h = 0; h < 16; h++) {
            float4 tv = *(const float4*)&t_s[h][m0];
            o.x = fmaf(w[h], tv.x, o.x);
            o.y = fmaf(w[h], tv.y, o.y);
            o.z = fmaf(w[h], tv.z, o.z);
            o.w = fmaf(w[h], tv.w, o.w);
        }
        *(float4*)(op + m0) = o;
        float vv[4];
        vv[0] = mk[m0+0] ? -1e30f : o.x;
        vv[1] = mk[m0+1] ? -1e30f : o.y;
        vv[2] = mk[m0+2] ? -1e30f : o.z;
        vv[3] = mk[m0+3] ? -1e30f : o.w;
#pragma unroll
        for (int c = 0; c < 4; c++) {
            float v = vv[c];
            if (v > M) {
                float sc = __expf(M - v);
                S1 = fmaf(S1, sc, 1.f);
                S2 = fmaf(S2, sc, v);
                M = v;
            } else {
                float ev = __expf(v - M);
                S1 += ev;
                S2 = fmaf(ev, v, S2);
            }
        }
    }
    // combine quad (4 mg for same e)
#pragma unroll
    for (int off = 1; off < 4; off <<= 1) {
        float Mo  = __shfl_xor_sync(0xffffffffu, M,  off);
        float S1o = __shfl_xor_sync(0xffffffffu, S1, off);
        float S2o = __shfl_xor_sync(0xffffffffu, S2, off);
        float Mn = fmaxf(M, Mo);
        float c1 = __expf(M - Mn), c2 = __expf(Mo - Mn);
        S1 = S1 * c1 + S1o * c2;
        S2 = S2 * c1 + S2o * c2;
        M = Mn;
    }
    if (mg == 0)
        g_wred[((size_t)b * 512 + n) * 64 + e] = S2 / S1;
}

// ---------------- node1 = a @ v per (b,h) ----------------
__global__ __launch_bounds__(256)
void node_kernel(const unsigned char* __restrict__ mask)
{
    __shared__ float a_s[64][68];
    __shared__ float v_s[64][33];
    __shared__ float Ms[64], Is[64];
    __shared__ unsigned char mk[512];
    const int tid = threadIdx.x;
    const int n0 = blockIdx.x << 6, h = blockIdx.y, b = blockIdx.z;
    const int bh = b * 16 + h;
    const float* ap = g_attn + (size_t)bh * 262144;
    const float* vp = g_v + (size_t)bh * 16384;
    const int d = tid & 31, nn = tid >> 5;

    if (tid < 64) { Ms[tid] = g_max[bh * 512 + n0 + tid]; Is[tid] = g_invden[bh * 512 + n0 + tid]; }
    for (int i = tid; i < 512; i += 256) mk[i] = mask[(b << 9) + i];
    __syncthreads();

    float acc[8];
#pragma unroll
    for (int i = 0; i < 8; i++) acc[i] = 0.f;

    for (int m0 = 0; m0 < 512; m0 += 64) {
        for (int i = tid; i < 1024; i += 256) {
            int r = i >> 4, c4 = (i & 15) << 2;
            float4 x = *(const float4*)(ap + (size_t)(n0 + r) * 512 + m0 + c4);
            float M = Ms[r], I = Is[r];
            a_s[r][c4+0] = mk[m0+c4+0] ? 0.f : __expf(x.x - M) * I;
            a_s[r][c4+1] = mk[m0+c4+1] ? 0.f : __expf(x.y - M) * I;
            a_s[r][c4+2] = mk[m0+c4+2] ? 0.f : __expf(x.z - M) * I;
            a_s[r][c4+3] = mk[m0+c4+3] ? 0.f : __expf(x.w - M) * I;
        }
        for (int i = tid; i < 512; i += 256) {
            int r = i >> 3, c4 = (i & 7) << 2;
            float4 x = *(const float4*)(vp + (size_t)(m0 + r) * 32 + c4);
            v_s[r][c4] = x.x; v_s[r][c4+1] = x.y; v_s[r][c4+2] = x.z; v_s[r][c4+3] = x.w;
        }
        __syncthreads();
#pragma unroll 4
        for (int m = 0; m < 64; m += 4) {
            float v0 = v_s[m][d], v1 = v_s[m+1][d], v2 = v_s[m+2][d], v3 = v_s[m+3][d];
#pragma unroll
            for (int i = 0; i < 8; i++) {
                float4 a4 = *(const float4*)&a_s[(nn << 3) + i][m];
                acc[i] = fmaf(a4.x, v0, acc[i]);
                acc[i] = fmaf(a4.y, v1, acc[i]);
                acc[i] = fmaf(a4.z, v2, acc[i]);
                acc[i] = fmaf(a4.w, v3, acc[i]);
            }
        }
        __syncthreads();
    }
    float* op = g_node1 + (size_t)(b * 512 + n0 + (nn << 3)) * 512 + h * 32 + d;
#pragma unroll
    for (int i = 0; i < 8; i++) op[(size_t)i * 512] = acc[i];
}

extern "C" void kernel_launch(void* const* d_in, const int* in_sizes, int n_in,
                              void* d_out, int out_size)
{
    const float* node_embeds = (const float*)d_in[0];
    const float* edge_embeds = (const float*)d_in[1];
    const unsigned char* padding_mask = (const unsigned char*)d_in[2];
    const float* qkv_w = (const float*)d_in[3];
    const float* qkv_b = (const float*)d_in[4];
    const float* reduce_w = (const float*)d_in[5];
    const float* reduce_b = (const float*)d_in[6];
    const float* expand_w = (const float*)d_in[7];
    const float* expand_b = (const float*)d_in[8];
    const float* fc_w = (const float*)d_in[9];
    const float* fc_b = (const float*)d_in[10];
    const float* proj_w = (const float*)d_in[11];
    const float* proj_b = (const float*)d_in[12];
    float* out = (float*)d_out;
    float* out_node = out;                 // [8,512,512]
    float* out_edge = out + 2097152;       // [8,64,512,512]

    sgemm_kernel<0><<<dim3(12, 32), 256>>>(node_embeds, qkv_w, qkv_b, nullptr, 512);
    bias_kernel<<<dim3(512, 8), 128>>>(edge_embeds, reduce_w, reduce_b);
    scores_kernel<<<dim3(8, 8, 128), 256>>>();
    stats_kernel<<<65536, 128>>>(padding_mask);
    edge_kernel<<<dim3(512, 8), 256>>>(padding_mask, expand_w, expand_b, out_edge);
    node_kernel<<<dim3(8, 16, 8), 256>>>(padding_mask);
    sgemm_kernel<1><<<dim3(4, 32), 256>>>(nullptr, fc_w, fc_b, nullptr, 64);
    sgemm_kernel<2><<<dim3(4, 32), 256>>>(nullptr, proj_w, proj_b, out_node, 512);
}

// round 3
// speedup vs baseline: 1.0582x; 1.0582x over previous
#include <cuda_runtime.h>
#include <cstdint>

#define SCALE_F 0.17677669529663687f

typedef unsigned long long u64;

__device__ __forceinline__ u64 pk2(float lo, float hi) {
    u64 r; asm("mov.b64 %0,{%1,%2};" : "=l"(r) : "f"(lo), "f"(hi)); return r;
}
__device__ __forceinline__ u64 bcast2(float v) { return pk2(v, v); }
__device__ __forceinline__ void upk2(u64 v, float &lo, float &hi) {
    asm("mov.b64 {%0,%1},%2;" : "=f"(lo), "=f"(hi) : "l"(v));
}
__device__ __forceinline__ u64 ffma2(u64 a, u64 b, u64 c) {
    u64 d; asm("fma.rn.f32x2 %0,%1,%2,%3;" : "=l"(d) : "l"(a), "l"(b), "l"(c)); return d;
}

// ---------------- scratch ----------------
__device__ float g_q[2097152];        // [B,H,N,D]
__device__ float g_k[2097152];
__device__ float g_v[2097152];
__device__ float g_attn[33554432];    // [B,H,N,N]
__device__ float g_max[65536];        // [B*H*N]
__device__ float g_invden[65536];
__device__ float g_node1[2097152];    // [B,N,C]
__device__ float g_wred[262144];      // [B,N,E]

// ---------------- generic 128x128 SGEMM: out = A @ W^T (+bias), FFMA2 ----------------
template<int EPI>
__global__ __launch_bounds__(256)
void sgemm_kernel(const float* __restrict__ A, const float* __restrict__ W,
                  const float* __restrict__ bias, float* __restrict__ Cout, int K)
{
    __shared__ float As[8][128];
    __shared__ float Ws[8][128];
    const int tid = threadIdx.x;
    const int bm = blockIdx.y << 7;
    const int bn = blockIdx.x << 7;
    const int lr = tid >> 1;
    const int lc = (tid & 1) << 2;
    const int tm = (tid >> 4) << 3;
    const int tn = (tid & 15) << 3;

    const float* Ab = (EPI == 1) ? (const float*)g_wred
                    : (EPI == 2) ? (const float*)g_node1 : A;

    u64 acc[4][8];
#pragma unroll
    for (int p = 0; p < 4; p++)
#pragma unroll
        for (int j = 0; j < 8; j++) acc[p][j] = 0ull;

    const float* Ap = Ab + (size_t)(bm + lr) * K + lc;
    const float* Wp = W  + (size_t)(bn + lr) * K + lc;

    for (int k0 = 0; k0 < K; k0 += 8) {
        float4 av = *(const float4*)(Ap + k0);
        float4 wv = *(const float4*)(Wp + k0);
        As[lc + 0][lr] = av.x; As[lc + 1][lr] = av.y;
        As[lc + 2][lr] = av.z; As[lc + 3][lr] = av.w;
        Ws[lc + 0][lr] = wv.x; Ws[lc + 1][lr] = wv.y;
        Ws[lc + 2][lr] = wv.z; Ws[lc + 3][lr] = wv.w;
        __syncthreads();
#pragma unroll
        for (int kk = 0; kk < 8; kk++) {
            ulonglong2 a01 = *(const ulonglong2*)&As[kk][tm];
            ulonglong2 a23 = *(const ulonglong2*)&As[kk][tm + 4];
            u64 ap[4] = {a01.x, a01.y, a23.x, a23.y};
            float4 t2 = *(const float4*)&Ws[kk][tn];
            float4 t3 = *(const float4*)&Ws[kk][tn + 4];
            u64 bb[8];
            bb[0] = bcast2(t2.x); bb[1] = bcast2(t2.y);
            bb[2] = bcast2(t2.z); bb[3] = bcast2(t2.w);
            bb[4] = bcast2(t3.x); bb[5] = bcast2(t3.y);
            bb[6] = bcast2(t3.z); bb[7] = bcast2(t3.w);
#pragma unroll
            for (int p = 0; p < 4; p++)
#pragma unroll
                for (int j = 0; j < 8; j++)
                    acc[p][j] = ffma2(ap[p], bb[j], acc[p][j]);
        }
        __syncthreads();
    }

    const int col0 = bn + tn;
    float4 bv0 = *(const float4*)&bias[col0];
    float4 bv1 = *(const float4*)&bias[col0 + 4];

#pragma unroll
    for (int p = 0; p < 4; p++) {
        float v2[2][8];
#pragma unroll
        for (int j = 0; j < 8; j++) upk2(acc[p][j], v2[0][j], v2[1][j]);
#pragma unroll
        for (int rr = 0; rr < 2; rr++) {
            const int row = bm + tm + 2 * p + rr;
            float4 o0, o1;
            o0.x = v2[rr][0] + bv0.x; o0.y = v2[rr][1] + bv0.y;
            o0.z = v2[rr][2] + bv0.z; o0.w = v2[rr][3] + bv0.w;
            o1.x = v2[rr][4] + bv1.x; o1.y = v2[rr][5] + bv1.y;
            o1.z = v2[rr][6] + bv1.z; o1.w = v2[rr][7] + bv1.w;
            if (EPI == 0) {
                int s  = col0 >> 9;
                int hd = col0 & 511;
                float* base = (s == 0 ? g_q : (s == 1 ? g_k : g_v));
                int b_ = row >> 9, n = row & 511;
                float* dst = base + ((size_t)((b_ << 4) + (hd >> 5)) << 14) + (n << 5) + (hd & 31);
                *(float4*)dst = o0; *(float4*)(dst + 4) = o1;
            } else {
                float* Cb = (EPI == 1) ? (float*)g_node1 : Cout;
                float* dst = Cb + ((size_t)row << 9) + col0;
                if (EPI == 1) {
                    float4 c0 = *(const float4*)dst;
                    float4 c1 = *(const float4*)(dst + 4);
                    o0.x += c0.x; o0.y += c0.y; o0.z += c0.z; o0.w += c0.w;
                    o1.x += c1.x; o1.y += c1.y; o1.z += c1.z; o1.w += c1.w;
                }
                *(float4*)dst = o0; *(float4*)(dst + 4) = o1;
            }
        }
    }
}

// ---------------- attn = sum_e edge[b,e,n,m]*rw[h,e] + rb[h] (FFMA2) ----------------
__global__ __launch_bounds__(128)
void bias_kernel(const float* __restrict__ edge, const float* __restrict__ rw,
                 const float* __restrict__ rb)
{
    __shared__ float s_rw[1024];
    __shared__ float s_rb[16];
    const int tid = threadIdx.x;
    const int n = blockIdx.x, b = blockIdx.y;
    for (int i = tid; i < 1024; i += 128) s_rw[i] = rw[i];
    if (tid < 16) s_rb[tid] = rb[tid];
    __syncthreads();

    const int m0 = tid << 2;
    u64 acc[16][2];
#pragma unroll
    for (int h = 0; h < 16; h++) { acc[h][0] = 0ull; acc[h][1] = 0ull; }

    const float* ep = edge + (size_t)b * 16777216 + (size_t)n * 512 + m0;
#pragma unroll 4
    for (int e = 0; e < 64; e++) {
        ulonglong2 v = *(const ulonglong2*)(ep + (size_t)e * 262144);
#pragma unroll
        for (int h = 0; h < 16; h++) {
            u64 w = bcast2(s_rw[(h << 6) + e]);
            acc[h][0] = ffma2(w, v.x, acc[h][0]);
            acc[h][1] = ffma2(w, v.y, acc[h][1]);
        }
    }
    float* op = g_attn + (size_t)b * 4194304 + (size_t)n * 512 + m0;
#pragma unroll
    for (int h = 0; h < 16; h++) {
        float rv = s_rb[h];
        float4 o;
        upk2(acc[h][0], o.x, o.y);
        upk2(acc[h][1], o.z, o.w);
        o.x += rv; o.y += rv; o.z += rv; o.w += rv;
        *(float4*)(op + (size_t)h * 262144) = o;
    }
}

// ---------------- attn += SCALE * q@k^T, per (b,h), 64x64 tiles, transposed smem ----------------
__global__ __launch_bounds__(256)
void scores_kernel()
{
    __shared__ float Qs[32][68];   // [d][n]
    __shared__ float Ks[32][68];   // [d][m]
    const int tid = threadIdx.x;
    const int bh = blockIdx.z;
    const int n0 = blockIdx.y << 6;
    const int m0 = blockIdx.x << 6;
    const float* qp = g_q + (size_t)bh * 16384;
    const float* kp = g_k + (size_t)bh * 16384;

    const int r = tid >> 2;
    const int c = (tid & 3) << 3;
    {
        float4 q1 = *(const float4*)(qp + (size_t)(n0 + r) * 32 + c);
        float4 q2 = *(const float4*)(qp + (size_t)(n0 + r) * 32 + c + 4);
        Qs[c+0][r]=q1.x; Qs[c+1][r]=q1.y; Qs[c+2][r]=q1.z; Qs[c+3][r]=q1.w;
        Qs[c+4][r]=q2.x; Qs[c+5][r]=q2.y; Qs[c+6][r]=q2.z; Qs[c+7][r]=q2.w;
        float4 k1 = *(const float4*)(kp + (size_t)(m0 + r) * 32 + c);
        float4 k2 = *(const float4*)(kp + (size_t)(m0 + r) * 32 + c + 4);
        Ks[c+0][r]=k1.x; Ks[c+1][r]=k1.y; Ks[c+2][r]=k1.z; Ks[c+3][r]=k1.w;
        Ks[c+4][r]=k2.x; Ks[c+5][r]=k2.y; Ks[c+6][r]=k2.z; Ks[c+7][r]=k2.w;
    }
    __syncthreads();

    const int tn = (tid >> 4) << 2;
    const int tm = (tid & 15) << 2;
    u64 acc[2][4];
#pragma unroll
    for (int p = 0; p < 2; p++)
#pragma unroll
        for (int j = 0; j < 4; j++) acc[p][j] = 0ull;

#pragma unroll
    for (int d = 0; d < 32; d++) {
        ulonglong2 av = *(const ulonglong2*)&Qs[d][tn];
        float4 bf = *(const float4*)&Ks[d][tm];
        u64 bb[4] = {bcast2(bf.x), bcast2(bf.y), bcast2(bf.z), bcast2(bf.w)};
        u64 ap[2] = {av.x, av.y};
#pragma unroll
        for (int p = 0; p < 2; p++)
#pragma unroll
            for (int j = 0; j < 4; j++)
                acc[p][j] = ffma2(ap[p], bb[j], acc[p][j]);
    }

#pragma unroll
    for (int p = 0; p < 2; p++) {
        float lo[4], hi[4];
#pragma unroll
        for (int j = 0; j < 4; j++) upk2(acc[p][j], lo[j], hi[j]);
#pragma unroll
        for (int rr = 0; rr < 2; rr++) {
            const float* src = rr ? hi : lo;
            float* op = g_attn + ((size_t)bh * 512 + n0 + tn + 2 * p + rr) * 512 + m0 + tm;
            float4 cur = *(float4*)op;
            cur.x += SCALE_F * src[0];
            cur.y += SCALE_F * src[1];
            cur.z += SCALE_F * src[2];
            cur.w += SCALE_F * src[3];
            *(float4*)op = cur;
        }
    }
}

// ---------------- softmax row stats over m (warp per row) ----------------
__global__ __launch_bounds__(256)
void stats_kernel(const unsigned char* __restrict__ mask)
{
    const int w = threadIdx.x >> 5, lane = threadIdx.x & 31;
    const int row = (blockIdx.x << 3) + w;          // (b*16+h)*512+n
    const int b = row >> 13;
    const float* ap = g_attn + (size_t)row * 512;
    const unsigned char* mp = mask + (b << 9);

    float x[16];
    bool km[16];
    float lm = -3.0e38f;
#pragma unroll
    for (int c = 0; c < 4; c++) {
        const int off = (lane << 2) + (c << 7);
        float4 v = *(const float4*)(ap + off);
        uchar4 m4 = *(const uchar4*)(mp + off);
        x[c*4+0] = v.x; x[c*4+1] = v.y; x[c*4+2] = v.z; x[c*4+3] = v.w;
        km[c*4+0] = m4.x != 0; km[c*4+1] = m4.y != 0;
        km[c*4+2] = m4.z != 0; km[c*4+3] = m4.w != 0;
#pragma unroll
        for (int j = 0; j < 4; j++) {
            float xv = km[c*4+j] ? -3.0e38f : x[c*4+j];
            lm = fmaxf(lm, xv);
        }
    }
#pragma unroll
    for (int off = 16; off > 0; off >>= 1)
        lm = fmaxf(lm, __shfl_xor_sync(0xffffffffu, lm, off));

    float ls = 0.f;
#pragma unroll
    for (int j = 0; j < 16; j++)
        if (!km[j]) ls += __expf(x[j] - lm);
#pragma unroll
    for (int off = 16; off > 0; off >>= 1)
        ls += __shfl_xor_sync(0xffffffffu, ls, off);

    if (lane == 0) { g_max[row] = lm; g_invden[row] = 1.0f / ls; }
}

// ---------------- edge path: t = a+attn; edge_out = expand(t)+eb; online edge softmax -> g_wred
__global__ __launch_bounds__(256)
void edge_kernel(const unsigned char* __restrict__ mask,
                 const float* __restrict__ ew, const float* __restrict__ eb,
                 float* __restrict__ out_edge)
{
    __shared__ float t_s[16][516];
    __shared__ float ewS[64][17];
    __shared__ float eb_s[64];
    __shared__ float M_s[16], L_s[16];
    __shared__ unsigned char mk[512];
    const int tid = threadIdx.x;
    const int n = blockIdx.x, b = blockIdx.y;

    for (int i = tid; i < 1024; i += 256) { ewS[i >> 4][i & 15] = ew[i]; }
    if (tid < 64) eb_s[tid] = eb[tid];
    if (tid < 16) {
        int row = (b * 16 + tid) * 512 + n;
        M_s[tid] = g_max[row];
        L_s[tid] = g_invden[row];
    }
    mk[tid] = mask[(b << 9) + tid];
    mk[tid + 256] = mask[(b << 9) + tid + 256];
    __syncthreads();

    // phase 1: t[h][m] = a + attn
    for (int mm = tid; mm < 512; mm += 256) {
        bool k = mk[mm] != 0;
        const float* ap = g_attn + (size_t)b * 4194304 + (size_t)n * 512 + mm;
#pragma unroll
        for (int h = 0; h < 16; h++) {
            float x = ap[(size_t)h * 262144];
            float a = k ? 0.f : __expf(x - M_s[h]) * L_s[h];
            t_s[h][mm] = a + x;
        }
    }
    __syncthreads();

    // phase 2: one e per 4 threads, 128 m each, FFMA2 + online softmax
    const int e = tid >> 2, mg = tid & 3;
    u64 wp[16];
#pragma unroll
    for (int h = 0; h < 16; h++) wp[h] = bcast2(ewS[e][h]);
    const float be = eb_s[e];
    const u64 be2 = bcast2(be);
    float* op = out_edge + ((size_t)b * 64 + e) * 262144 + (size_t)n * 512;

    float M = -1e30f, S1 = 0.f, S2 = 0.f;
#pragma unroll 4
    for (int j = 0; j < 32; j++) {
        const int m0 = (mg << 2) + (j << 4);
        u64 o0 = be2, o1 = be2;
#pragma unroll
        for (int h = 0; h < 16; h++) {
            ulonglong2 tv = *(const ulonglong2*)&t_s[h][m0];
            o0 = ffma2(wp[h], tv.x, o0);
            o1 = ffma2(wp[h], tv.y, o1);
        }
        float4 o;
        upk2(o0, o.x, o.y);
        upk2(o1, o.z, o.w);
        *(float4*)(op + m0) = o;
        float vv[4];
        vv[0] = mk[m0+0] ? -1e30f : o.x;
        vv[1] = mk[m0+1] ? -1e30f : o.y;
        vv[2] = mk[m0+2] ? -1e30f : o.z;
        vv[3] = mk[m0+3] ? -1e30f : o.w;
#pragma unroll
        for (int c = 0; c < 4; c++) {
            float v = vv[c];
            if (v > M) {
                float sc = __expf(M - v);
                S1 = fmaf(S1, sc, 1.f);
                S2 = fmaf(S2, sc, v);
                M = v;
            } else {
                float ev = __expf(v - M);
                S1 += ev;
                S2 = fmaf(ev, v, S2);
            }
        }
    }
#pragma unroll
    for (int off = 1; off < 4; off <<= 1) {
        float Mo  = __shfl_xor_sync(0xffffffffu, M,  off);
        float S1o = __shfl_xor_sync(0xffffffffu, S1, off);
        float S2o = __shfl_xor_sync(0xffffffffu, S2, off);
        float Mn = fmaxf(M, Mo);
        float c1 = __expf(M - Mn), c2 = __expf(Mo - Mn);
        S1 = S1 * c1 + S1o * c2;
        S2 = S2 * c1 + S2o * c2;
        M = Mn;
    }
    if (mg == 0)
        g_wred[((size_t)b * 512 + n) * 64 + e] = S2 / S1;
}

// ---------------- node1 = a @ v per (b,h), FFMA2 ----------------
__global__ __launch_bounds__(256)
void node_kernel(const unsigned char* __restrict__ mask)
{
    __shared__ float a_s[64][68];
    __shared__ float v_s[64][33];
    __shared__ float Ms[64], Is[64];
    __shared__ unsigned char mk[512];
    const int tid = threadIdx.x;
    const int n0 = blockIdx.x << 6, h = blockIdx.y, b = blockIdx.z;
    const int bh = b * 16 + h;
    const float* ap = g_attn + (size_t)bh * 262144;
    const float* vp = g_v + (size_t)bh * 16384;
    const int d = tid & 31, nn = tid >> 5;

    if (tid < 64) { Ms[tid] = g_max[bh * 512 + n0 + tid]; Is[tid] = g_invden[bh * 512 + n0 + tid]; }
    for (int i = tid; i < 512; i += 256) mk[i] = mask[(b << 9) + i];
    __syncthreads();

    u64 acc2[8];
#pragma unroll
    for (int i = 0; i < 8; i++) acc2[i] = 0ull;

    for (int m0 = 0; m0 < 512; m0 += 64) {
        for (int i = tid; i < 1024; i += 256) {
            int r = i >> 4, c4 = (i & 15) << 2;
            float4 x = *(const float4*)(ap + (size_t)(n0 + r) * 512 + m0 + c4);
            float M = Ms[r], I = Is[r];
            a_s[r][c4+0] = mk[m0+c4+0] ? 0.f : __expf(x.x - M) * I;
            a_s[r][c4+1] = mk[m0+c4+1] ? 0.f : __expf(x.y - M) * I;
            a_s[r][c4+2] = mk[m0+c4+2] ? 0.f : __expf(x.z - M) * I;
            a_s[r][c4+3] = mk[m0+c4+3] ? 0.f : __expf(x.w - M) * I;
        }
        for (int i = tid; i < 512; i += 256) {
            int r = i >> 3, c4 = (i & 7) << 2;
            float4 x = *(const float4*)(vp + (size_t)(m0 + r) * 32 + c4);
            v_s[r][c4] = x.x; v_s[r][c4+1] = x.y; v_s[r][c4+2] = x.z; v_s[r][c4+3] = x.w;
        }
        __syncthreads();
#pragma unroll 4
        for (int m = 0; m < 64; m += 4) {
            u64 vp0 = pk2(v_s[m][d],   v_s[m+1][d]);
            u64 vp1 = pk2(v_s[m+2][d], v_s[m+3][d]);
#pragma unroll
            for (int i = 0; i < 8; i++) {
                ulonglong2 a2 = *(const ulonglong2*)&a_s[(nn << 3) + i][m];
                acc2[i] = ffma2(a2.x, vp0, acc2[i]);
                acc2[i] = ffma2(a2.y, vp1, acc2[i]);
            }
        }
        __syncthreads();
    }
    float* op = g_node1 + (size_t)(b * 512 + n0 + (nn << 3)) * 512 + h * 32 + d;
#pragma unroll
    for (int i = 0; i < 8; i++) {
        float lo, hi;
        upk2(acc2[i], lo, hi);
        op[(size_t)i * 512] = lo + hi;
    }
}

extern "C" void kernel_launch(void* const* d_in, const int* in_sizes, int n_in,
                              void* d_out, int out_size)
{
    const float* node_embeds = (const float*)d_in[0];
    const float* edge_embeds = (const float*)d_in[1];
    const unsigned char* padding_mask = (const unsigned char*)d_in[2];
    const float* qkv_w = (const float*)d_in[3];
    const float* qkv_b = (const float*)d_in[4];
    const float* reduce_w = (const float*)d_in[5];
    const float* reduce_b = (const float*)d_in[6];
    const float* expand_w = (const float*)d_in[7];
    const float* expand_b = (const float*)d_in[8];
    const float* fc_w = (const float*)d_in[9];
    const float* fc_b = (const float*)d_in[10];
    const float* proj_w = (const float*)d_in[11];
    const float* proj_b = (const float*)d_in[12];
    float* out = (float*)d_out;
    float* out_node = out;                 // [8,512,512]
    float* out_edge = out + 2097152;       // [8,64,512,512]

    sgemm_kernel<0><<<dim3(12, 32), 256>>>(node_embeds, qkv_w, qkv_b, nullptr, 512);
    bias_kernel<<<dim3(512, 8), 128>>>(edge_embeds, reduce_w, reduce_b);
    scores_kernel<<<dim3(8, 8, 128), 256>>>();
    stats_kernel<<<8192, 256>>>(padding_mask);
    edge_kernel<<<dim3(512, 8), 256>>>(padding_mask, expand_w, expand_b, out_edge);
    node_kernel<<<dim3(8, 16, 8), 256>>>(padding_mask);
    sgemm_kernel<1><<<dim3(4, 32), 256>>>(nullptr, fc_w, fc_b, nullptr, 64);
    sgemm_kernel<2><<<dim3(4, 32), 256>>>(nullptr, proj_w, proj_b, out_node, 512);
}